// round 4
// baseline (speedup 1.0000x reference)
#include <cuda_runtime.h>
#include <cuda_bf16.h>

// Problem constants (HiePoolingLayer): nn_outs (B,T,E) f32, batch_x (B,T) int
#define B 32
#define T 4096
#define E 256
#define E4 (E / 4)   // 64 float4 lanes per token row

// __device__ scratch (no dynamic allocation allowed)
__device__ int g_cut_pos[B][T];   // token index of k-th cut in row b
__device__ int g_ncuts[B];        // number of cuts (segments) in row b
__device__ int g_is_i32;          // 1 if batch_x is int32 layout, 0 if int64

// ---------------------------------------------------------------------------
// Kernel 0a: reset detection flag (graph-replay safe: recomputed every call).
// ---------------------------------------------------------------------------
__global__ void reset_flag_kernel() { g_is_i32 = 0; }

// ---------------------------------------------------------------------------
// Kernel 0b: dtype detection. View batch_x as int32[B*T] (safe for both
// layouts). If ANY odd-index word is nonzero -> int32 layout (cut tokens sit
// at odd indices 15,31,...). If int64 layout, odd words are hi-halves of 0/1
// values and are all zero.
// ---------------------------------------------------------------------------
__global__ void detect_dtype_kernel(const int* __restrict__ bx32) {
    const int n_odd = (B * T) / 2;
    int idx = blockIdx.x * blockDim.x + threadIdx.x;
    int any = 0;
    for (int i = idx; i < n_odd; i += gridDim.x * blockDim.x) {
        any |= bx32[2 * i + 1];
    }
    any = __syncthreads_or(any != 0);
    if (threadIdx.x == 0 && any) atomicOr(&g_is_i32, 1);
}

// ---------------------------------------------------------------------------
// Kernel 1: per-row scan of cut flags -> cut positions + counts.
// One block per row, 256 threads x 16 tokens each.
// ---------------------------------------------------------------------------
__global__ void find_cuts_kernel(const int* __restrict__ bx32) {
    const int b = blockIdx.x;
    const int is32 = g_is_i32;

    const int tid  = threadIdx.x;
    const int base = tid * 16;

    unsigned mask = 0;
    int cnt = 0;
    if (is32) {
        const int* row = bx32 + (size_t)b * T;
#pragma unroll
        for (int i = 0; i < 16; i++) {
            if (row[base + i] == 1) { mask |= (1u << i); cnt++; }
        }
    } else {
        const int* row = bx32 + (size_t)b * T * 2;
#pragma unroll
        for (int i = 0; i < 16; i++) {
            if (row[2 * (base + i)] == 1 && row[2 * (base + i) + 1] == 0) {
                mask |= (1u << i); cnt++;
            }
        }
    }

    // warp inclusive scan of cnt
    const int lane = tid & 31;
    const int wid  = tid >> 5;
    int x = cnt;
#pragma unroll
    for (int o = 1; o < 32; o <<= 1) {
        int y = __shfl_up_sync(0xFFFFFFFFu, x, o);
        if (lane >= o) x += y;
    }

    __shared__ int wsum[8];
    if (lane == 31) wsum[wid] = x;
    __syncthreads();

    int wexcl = 0;
    for (int i = 0; i < wid; i++) wexcl += wsum[i];

    int excl = wexcl + x - cnt;   // exclusive prefix (rank of my first cut)

    int r = excl;
#pragma unroll
    for (int i = 0; i < 16; i++) {
        if ((mask >> i) & 1u) {
            g_cut_pos[b][r++] = base + i;
        }
    }

    if (tid == blockDim.x - 1) {
        g_ncuts[b] = excl + cnt;   // total cuts in this row
    }
}

// ---------------------------------------------------------------------------
// Kernel 2: pool one segment per block. 64 threads, each owns one float4
// column of E. Reads are 1KB coalesced per token row.
// ---------------------------------------------------------------------------
__global__ __launch_bounds__(E4) void pool_kernel(const float* __restrict__ nn,
                                                  float* __restrict__ out,
                                                  int maxlen) {
    const int seg = blockIdx.x % maxlen;
    const int b   = blockIdx.x / maxlen;
    const int tid = threadIdx.x;

    float4* o = (float4*)out + ((size_t)b * maxlen + seg) * E4 + tid;

    const int nc = g_ncuts[b];
    if (seg >= nc) {
        // pad segment: reference yields exact zeros (sums=0 / max(0,1))
        *o = make_float4(0.f, 0.f, 0.f, 0.f);
        return;
    }

    const int end   = g_cut_pos[b][seg];                       // inclusive
    const int start = (seg > 0) ? (g_cut_pos[b][seg - 1] + 1) : 0;
    const int len   = end - start + 1;

    const float4* src = (const float4*)(nn + ((size_t)b * T + start) * E) + tid;

    float4 acc = make_float4(0.f, 0.f, 0.f, 0.f);
#pragma unroll 4
    for (int t = 0; t < len; t++) {
        float4 v = src[(size_t)t * E4];
        acc.x += v.x; acc.y += v.y; acc.z += v.z; acc.w += v.w;
    }

    const float inv = 1.0f / (float)len;
    acc.x *= inv; acc.y *= inv; acc.z *= inv; acc.w *= inv;
    *o = acc;
}

// ---------------------------------------------------------------------------
// Kernel 3 (tail): write n_cuts after pooled block.
// tail_mode 1: B elements of the (float32) output dtype -> write as float.
// tail_mode 2: int64 tail (2B f32-slots) -> write as int64.
// ---------------------------------------------------------------------------
__global__ void write_ncuts_f32_kernel(float* __restrict__ out, size_t off) {
    int i = threadIdx.x;
    if (i < B) out[off + i] = (float)g_ncuts[i];
}

__global__ void write_ncuts_i64_kernel(long long* __restrict__ out64, size_t off64) {
    int i = threadIdx.x;
    if (i < B) out64[off64 + i] = (long long)g_ncuts[i];
}

extern "C" void kernel_launch(void* const* d_in, const int* in_sizes, int n_in,
                              void* d_out, int out_size) {
    // Defensive input-order check: nn_outs has B*T*E elements, batch_x B*T.
    int i_nn = 0, i_bx = 1;
    if (n_in >= 2 && in_sizes[0] == B * T && in_sizes[1] != B * T) {
        i_nn = 1; i_bx = 0;
    }
    const float* nn   = (const float*)d_in[i_nn];    // (B,T,E) f32
    const int*   bx32 = (const int*)d_in[i_bx];      // (B,T) i32 or i64 view
    float*       out  = (float*)d_out;

    // Derive maxlen (and optional n_cuts tail) from out_size.
    const long long bE = (long long)B * E;
    int maxlen = 0;
    int tail_mode = 0;  // 0=none, 1=B output-dtype elems (float), 2=i64 tail
    if (out_size % bE == 0) {
        maxlen = (int)(out_size / bE);
    } else if ((out_size - B) % bE == 0) {
        maxlen = (int)((out_size - B) / bE);
        tail_mode = 1;
    } else if ((out_size - 2 * B) % bE == 0) {
        maxlen = (int)((out_size - 2 * B) / bE);
        tail_mode = 2;
    } else {
        maxlen = T / 16;  // fallback: uniform stride-16 cuts
    }

    reset_flag_kernel<<<1, 1>>>();
    detect_dtype_kernel<<<64, 256>>>(bx32);
    find_cuts_kernel<<<B, 256>>>(bx32);
    pool_kernel<<<B * maxlen, E4>>>(nn, out, maxlen);

    if (tail_mode == 1) {
        write_ncuts_f32_kernel<<<1, 32>>>(out, (size_t)B * maxlen * E);
    } else if (tail_mode == 2) {
        write_ncuts_i64_kernel<<<1, 32>>>((long long*)d_out,
                                          ((size_t)B * maxlen * E) / 2);
    }
}

// round 5
// speedup vs baseline: 1.1135x; 1.1135x over previous
#include <cuda_runtime.h>
#include <cuda_bf16.h>

// Problem constants (HiePoolingLayer): nn_outs (B,T,E) f32, batch_x (B,T) int
#define B 32
#define T 4096
#define E 256
#define E4 (E / 4)   // 64 float4 lanes per token row

// __device__ scratch (no dynamic allocation allowed)
__device__ int g_cut_pos[B][T];   // token index of k-th cut in row b
__device__ int g_ncuts[B];        // number of cuts (segments) in row b

// ---------------------------------------------------------------------------
// Kernel 1 (fused prep): per-row dtype detection + cut scan + ncuts + tail.
// One block per row, 256 threads x 16 words each.
//
// Layout detection is per-block but globally consistent:
//  - int32 layout: words [bT,(b+1)T) are row b's tokens; cuts sit at odd word
//    indices (15,31,...) -> some odd word nonzero.
//  - int64 layout: words [bT,(b+1)T) are lo/hi pairs of 0/1 values; every odd
//    word (hi half) is zero.
// ---------------------------------------------------------------------------
__global__ __launch_bounds__(256) void prep_kernel(const int* __restrict__ bx32,
                                                   float* __restrict__ out,
                                                   long long tail_off,
                                                   int tail_mode) {
    const int b    = blockIdx.x;
    const int tid  = threadIdx.x;
    const int base = tid * 16;

    // load my 16 words of the int32 view of this row's slice
    int v[16];
    const int* slice = bx32 + (size_t)b * T;
#pragma unroll
    for (int i = 0; i < 16; i++) v[i] = slice[base + i];

    // detect: any odd-index word nonzero -> int32 layout
    int odd_any = 0;
#pragma unroll
    for (int i = 1; i < 16; i += 2) odd_any |= v[i];
    const int is32 = __syncthreads_or(odd_any != 0);

    // build cut mask for my 16 tokens
    unsigned mask = 0;
    int cnt = 0;
    if (is32) {
#pragma unroll
        for (int i = 0; i < 16; i++) {
            if (v[i] == 1) { mask |= (1u << i); cnt++; }
        }
    } else {
        const int* row64 = bx32 + (size_t)b * T * 2;
#pragma unroll
        for (int i = 0; i < 16; i++) {
            if (row64[2 * (base + i)] == 1 && row64[2 * (base + i) + 1] == 0) {
                mask |= (1u << i); cnt++;
            }
        }
    }

    // warp inclusive scan of cnt
    const int lane = tid & 31;
    const int wid  = tid >> 5;
    int x = cnt;
#pragma unroll
    for (int o = 1; o < 32; o <<= 1) {
        int y = __shfl_up_sync(0xFFFFFFFFu, x, o);
        if (lane >= o) x += y;
    }

    __shared__ int wsum[8];
    if (lane == 31) wsum[wid] = x;
    __syncthreads();

    int wexcl = 0;
    for (int i = 0; i < wid; i++) wexcl += wsum[i];

    const int excl = wexcl + x - cnt;   // rank of my first cut

    int r = excl;
#pragma unroll
    for (int i = 0; i < 16; i++) {
        if ((mask >> i) & 1u) {
            g_cut_pos[b][r++] = base + i;
        }
    }

    if (tid == blockDim.x - 1) {
        const int total = excl + cnt;
        g_ncuts[b] = total;
        // tail write (n_cuts output), fused here to save a launch
        if (tail_mode == 1) {
            out[tail_off + b] = (float)total;           // f32 output dtype
        } else if (tail_mode == 2) {
            ((long long*)out)[tail_off / 2 + b] = (long long)total;  // i64
        }
    }
}

// ---------------------------------------------------------------------------
// Kernel 2: pool. 256-thread blocks = 4 groups of 64 lanes; each group
// handles SEGS_PER_GROUP consecutive segments. Total threads ~0.86 waves
// (single wave, no wave-transition tail). Loads hand-batched 4-wide.
// ---------------------------------------------------------------------------
#define SEGS_PER_GROUP 2

__global__ __launch_bounds__(256) void pool_kernel(const float* __restrict__ nn,
                                                   float* __restrict__ out,
                                                   int maxlen) {
    const int grp  = blockIdx.x * 4 + (threadIdx.x >> 6);
    const int lane = threadIdx.x & 63;
    const int nseg = B * maxlen;

#pragma unroll
    for (int s = 0; s < SEGS_PER_GROUP; s++) {
        const int flat = grp * SEGS_PER_GROUP + s;
        if (flat >= nseg) return;
        const int b   = flat / maxlen;
        const int seg = flat % maxlen;

        float4* o = (float4*)out + (size_t)flat * E4 + lane;

        const int nc = g_ncuts[b];
        if (seg >= nc) {
            *o = make_float4(0.f, 0.f, 0.f, 0.f);   // pad segment -> zeros
            continue;
        }

        const int end   = g_cut_pos[b][seg];                     // inclusive
        const int start = (seg > 0) ? (g_cut_pos[b][seg - 1] + 1) : 0;
        const int len   = end - start + 1;

        const float4* src = (const float4*)(nn + ((size_t)b * T + start) * E) + lane;

        float4 acc = make_float4(0.f, 0.f, 0.f, 0.f);
        int t = 0;
        // 4-wide batched loads: 4 independent LDG.128 in flight per batch
        for (; t + 4 <= len; t += 4) {
            float4 v0 = src[(size_t)(t + 0) * E4];
            float4 v1 = src[(size_t)(t + 1) * E4];
            float4 v2 = src[(size_t)(t + 2) * E4];
            float4 v3 = src[(size_t)(t + 3) * E4];
            acc.x += v0.x + v1.x + v2.x + v3.x;
            acc.y += v0.y + v1.y + v2.y + v3.y;
            acc.z += v0.z + v1.z + v2.z + v3.z;
            acc.w += v0.w + v1.w + v2.w + v3.w;
        }
        for (; t < len; t++) {
            float4 v = src[(size_t)t * E4];
            acc.x += v.x; acc.y += v.y; acc.z += v.z; acc.w += v.w;
        }

        const float inv = 1.0f / (float)len;
        acc.x *= inv; acc.y *= inv; acc.z *= inv; acc.w *= inv;
        *o = acc;
    }
}

extern "C" void kernel_launch(void* const* d_in, const int* in_sizes, int n_in,
                              void* d_out, int out_size) {
    // Defensive input-order check: nn_outs has B*T*E elements, batch_x B*T.
    int i_nn = 0, i_bx = 1;
    if (n_in >= 2 && in_sizes[0] == B * T && in_sizes[1] != B * T) {
        i_nn = 1; i_bx = 0;
    }
    const float* nn   = (const float*)d_in[i_nn];    // (B,T,E) f32
    const int*   bx32 = (const int*)d_in[i_bx];      // (B,T) i32 or i64 view
    float*       out  = (float*)d_out;

    // Derive maxlen (and optional n_cuts tail) from out_size.
    const long long bE = (long long)B * E;
    int maxlen = 0;
    int tail_mode = 0;  // 0=none, 1=B output-dtype elems (float), 2=i64 tail
    if (out_size % bE == 0) {
        maxlen = (int)(out_size / bE);
    } else if ((out_size - B) % bE == 0) {
        maxlen = (int)((out_size - B) / bE);
        tail_mode = 1;
    } else if ((out_size - 2 * B) % bE == 0) {
        maxlen = (int)((out_size - 2 * B) / bE);
        tail_mode = 2;
    } else {
        maxlen = T / 16;  // fallback: uniform stride-16 cuts
    }

    const long long tail_off = (long long)B * maxlen * E;

    prep_kernel<<<B, 256>>>(bx32, out, tail_off, tail_mode);

    const int ngroups = (B * maxlen + SEGS_PER_GROUP - 1) / SEGS_PER_GROUP;
    const int nblocks = (ngroups + 3) / 4;
    pool_kernel<<<nblocks, 256>>>(nn, out, maxlen);
}

// round 6
// speedup vs baseline: 1.2246x; 1.0997x over previous
#include <cuda_runtime.h>
#include <cuda_bf16.h>

// Problem constants (HiePoolingLayer): nn_outs (B,T,E) f32, batch_x (B,T) int
#define B 32
#define T 4096
#define E 256
#define E4 (E / 4)   // 64 float4 lanes per token row

// __device__ scratch (no dynamic allocation allowed)
__device__ int g_cut_pos[B][T];   // token index of k-th cut in row b
__device__ int g_ncuts[B];        // number of cuts (segments) in row b

// ---------------------------------------------------------------------------
// Kernel 1 (fused prep): per-row dtype detection + cut scan + ncuts + tail.
// One block per row, 256 threads x 16 words each.
//
// Layout detection is per-block but globally consistent:
//  - int32 layout: words [bT,(b+1)T) are row b's tokens; cuts sit at odd word
//    indices -> some odd word nonzero.
//  - int64 layout: odd words are hi-halves of 0/1 values -> all zero.
// ---------------------------------------------------------------------------
__global__ __launch_bounds__(256) void prep_kernel(const int* __restrict__ bx32,
                                                   float* __restrict__ out,
                                                   long long tail_off,
                                                   int tail_mode) {
    const int b    = blockIdx.x;
    const int tid  = threadIdx.x;
    const int base = tid * 16;

    int v[16];
    const int* slice = bx32 + (size_t)b * T;
#pragma unroll
    for (int i = 0; i < 16; i++) v[i] = slice[base + i];

    int odd_any = 0;
#pragma unroll
    for (int i = 1; i < 16; i += 2) odd_any |= v[i];
    const int is32 = __syncthreads_or(odd_any != 0);

    unsigned mask = 0;
    int cnt = 0;
    if (is32) {
#pragma unroll
        for (int i = 0; i < 16; i++) {
            if (v[i] == 1) { mask |= (1u << i); cnt++; }
        }
    } else {
        const int* row64 = bx32 + (size_t)b * T * 2;
#pragma unroll
        for (int i = 0; i < 16; i++) {
            if (row64[2 * (base + i)] == 1 && row64[2 * (base + i) + 1] == 0) {
                mask |= (1u << i); cnt++;
            }
        }
    }

    // warp inclusive scan of cnt
    const int lane = tid & 31;
    const int wid  = tid >> 5;
    int x = cnt;
#pragma unroll
    for (int o = 1; o < 32; o <<= 1) {
        int y = __shfl_up_sync(0xFFFFFFFFu, x, o);
        if (lane >= o) x += y;
    }

    __shared__ int wsum[8];
    if (lane == 31) wsum[wid] = x;
    __syncthreads();

    int wexcl = 0;
    for (int i = 0; i < wid; i++) wexcl += wsum[i];

    const int excl = wexcl + x - cnt;   // rank of my first cut

    int r = excl;
#pragma unroll
    for (int i = 0; i < 16; i++) {
        if ((mask >> i) & 1u) {
            g_cut_pos[b][r++] = base + i;
        }
    }

    if (tid == blockDim.x - 1) {
        const int total = excl + cnt;
        g_ncuts[b] = total;
        if (tail_mode == 1) {
            out[tail_off + b] = (float)total;           // f32 output dtype
        } else if (tail_mode == 2) {
            ((long long*)out)[tail_off / 2 + b] = (long long)total;  // i64
        }
    }
}

// ---------------------------------------------------------------------------
// Kernel 2: pool. 64-thread blocks (R4's proven shape: 32 regs, 32 blocks/SM
// = 100% occupancy), persistent grid-stride over segments -> one wave.
// Launched with PDL: blocks spin up during prep; GridDependencySynchronize
// makes prep's scratch writes visible before use.
// ---------------------------------------------------------------------------
__global__ __launch_bounds__(E4) void pool_kernel(const float* __restrict__ nn,
                                                  float* __restrict__ out,
                                                  int maxlen) {
    cudaGridDependencySynchronize();

    const int nseg = B * maxlen;
    const int tid  = threadIdx.x;

    for (int flat = blockIdx.x; flat < nseg; flat += gridDim.x) {
        const int b   = flat / maxlen;
        const int seg = flat % maxlen;

        float4* o = (float4*)out + (size_t)flat * E4 + tid;

        const int nc = g_ncuts[b];
        if (seg >= nc) {
            *o = make_float4(0.f, 0.f, 0.f, 0.f);   // pad segment -> zeros
            continue;
        }

        const int end   = g_cut_pos[b][seg];                     // inclusive
        const int start = (seg > 0) ? (g_cut_pos[b][seg - 1] + 1) : 0;
        const int len   = end - start + 1;

        const float4* src = (const float4*)(nn + ((size_t)b * T + start) * E) + tid;

        float4 acc = make_float4(0.f, 0.f, 0.f, 0.f);
#pragma unroll 4
        for (int t = 0; t < len; t++) {
            float4 v = src[(size_t)t * E4];
            acc.x += v.x; acc.y += v.y; acc.z += v.z; acc.w += v.w;
        }

        const float inv = 1.0f / (float)len;
        acc.x *= inv; acc.y *= inv; acc.z *= inv; acc.w *= inv;
        *o = acc;
    }
}

extern "C" void kernel_launch(void* const* d_in, const int* in_sizes, int n_in,
                              void* d_out, int out_size) {
    // Defensive input-order check: nn_outs has B*T*E elements, batch_x B*T.
    int i_nn = 0, i_bx = 1;
    if (n_in >= 2 && in_sizes[0] == B * T && in_sizes[1] != B * T) {
        i_nn = 1; i_bx = 0;
    }
    const float* nn   = (const float*)d_in[i_nn];    // (B,T,E) f32
    const int*   bx32 = (const int*)d_in[i_bx];      // (B,T) i32 or i64 view
    float*       out  = (float*)d_out;

    // Derive maxlen (and optional n_cuts tail) from out_size.
    const long long bE = (long long)B * E;
    int maxlen = 0;
    int tail_mode = 0;  // 0=none, 1=B output-dtype elems (float), 2=i64 tail
    if (out_size % bE == 0) {
        maxlen = (int)(out_size / bE);
    } else if ((out_size - B) % bE == 0) {
        maxlen = (int)((out_size - B) / bE);
        tail_mode = 1;
    } else if ((out_size - 2 * B) % bE == 0) {
        maxlen = (int)((out_size - 2 * B) / bE);
        tail_mode = 2;
    } else {
        maxlen = T / 16;  // fallback: uniform stride-16 cuts
    }

    const long long tail_off = (long long)B * maxlen * E;

    prep_kernel<<<B, 256>>>(bx32, out, tail_off, tail_mode);

    // Persistent single-wave grid: 148 SMs x 32 blocks of 64 threads.
    int nseg   = B * maxlen;
    int nblocks = 148 * 32;
    if (nblocks > nseg) nblocks = nseg;

    // PDL launch: overlap pool's block rollout with prep's tail.
    cudaLaunchConfig_t cfg = {};
    cfg.gridDim  = dim3((unsigned)nblocks, 1, 1);
    cfg.blockDim = dim3(E4, 1, 1);
    cfg.dynamicSmemBytes = 0;
    cfg.stream = 0;
    cudaLaunchAttribute attrs[1];
    attrs[0].id = cudaLaunchAttributeProgrammaticStreamSerialization;
    attrs[0].val.programmaticStreamSerializationAllowed = 1;
    cfg.attrs = attrs;
    cfg.numAttrs = 1;
    cudaError_t err = cudaLaunchKernelEx(&cfg, pool_kernel, nn, out, maxlen);
    if (err != cudaSuccess) {
        // Fallback: plain launch (still correct, just serialized).
        pool_kernel<<<nblocks, E4>>>(nn, out, maxlen);
    }
}